// round 7
// baseline (speedup 1.0000x reference)
#include <cuda_runtime.h>
#include <cstdint>

#define N_NODES 50000
#define E_EDGES 800000
#define D_DIM   128
#define L_LAYERS 3

// Scratch (static __device__ arrays: allocation-free per harness rules).
__device__ __align__(16) float g_Z[N_NODES * D_DIM];  // Z = (1+eps)*X + S
__device__ __align__(16) float g_H[N_NODES * D_DIM];  // hidden after ReLU
__device__ __align__(16) float g_X[N_NODES * D_DIM];  // ping buffer between layers
__device__ int g_is_i64;                              // edge_index dtype flag

// ---------------------------------------------------------------------------
// packed f32x2 helpers (Blackwell sm_103a)
// ---------------------------------------------------------------------------
__device__ __forceinline__ unsigned long long pack2(float a, float b) {
    unsigned long long r;
    asm("mov.b64 %0, {%1, %2};" : "=l"(r) : "f"(a), "f"(b));
    return r;
}
__device__ __forceinline__ unsigned long long fma2(unsigned long long a,
                                                   unsigned long long b,
                                                   unsigned long long c) {
    unsigned long long r;
    asm("fma.rn.f32x2 %0, %1, %2, %3;" : "=l"(r) : "l"(a), "l"(b), "l"(c));
    return r;
}
__device__ __forceinline__ float2 unpack2(unsigned long long v) {
    float2 r;
    asm("mov.b64 {%0, %1}, %2;" : "=f"(r.x), "=f"(r.y) : "l"(v));
    return r;
}

// ---------------------------------------------------------------------------
// Dtype probe: interpret first 2048 entries as int64. True int64 indices all
// lie in [0, N). If the array is really int32, each 8B read fuses two random
// indices a + b*2^32 (in-range only if b==0, p=2e-5) -> detection certain.
// Deterministic, device-only, graph-capturable.
// ---------------------------------------------------------------------------
__global__ void detect_dtype_kernel(const void* ei) {
    const long long* e64 = (const long long*)ei;
    int bad = 0;
    for (int i = threadIdx.x; i < 2048; i += 256) {
        long long v = e64[i];
        if (v < 0 || v >= N_NODES) bad = 1;
    }
    bad = __syncthreads_or(bad);
    if (threadIdx.x == 0) g_is_i64 = bad ? 0 : 1;
}

// ---------------------------------------------------------------------------
// Z = (1 + eps[layer]) * X
// ---------------------------------------------------------------------------
__global__ void init_z_kernel(const float* __restrict__ X,
                              const float* __restrict__ eps, int layer) {
    int i = blockIdx.x * blockDim.x + threadIdx.x;
    const int total = N_NODES * D_DIM / 4;
    if (i >= total) return;
    float s = 1.0f + __ldg(eps + layer);
    float4 v = ((const float4*)X)[i];
    v.x *= s; v.y *= s; v.z *= s; v.w *= s;
    ((float4*)g_Z)[i] = v;
}

// ---------------------------------------------------------------------------
// Scatter-add: one warp per edge. Lane l handles columns [4l, 4l+4).
// Coalesced 512B gather of X[src]; 16B vector red to Z[dst].
// edge_index layout (2, E) row-major: src = ei[0:E), dst = ei[E:2E).
// Index dtype resolved at runtime via g_is_i64.
// ---------------------------------------------------------------------------
__global__ void scatter_kernel(const float* __restrict__ X,
                               const void* __restrict__ ei) {
    unsigned e = (blockIdx.x * blockDim.x + threadIdx.x) >> 5;
    unsigned lane = threadIdx.x & 31u;
    if (e >= E_EDGES) return;
    int s, d;
    if (g_is_i64) {
        const long long* e64 = (const long long*)ei;
        s = (int)e64[e];
        d = (int)e64[E_EDGES + e];
    } else {
        const int* e32 = (const int*)ei;
        s = e32[e];
        d = e32[E_EDGES + e];
    }
    float4 v = ((const float4*)(X + (size_t)s * D_DIM))[lane];
    float* p = g_Z + (size_t)d * D_DIM + lane * 4;
    asm volatile("red.global.add.v4.f32 [%0], {%1, %2, %3, %4};"
                 :: "l"(p), "f"(v.x), "f"(v.y), "f"(v.z), "f"(v.w)
                 : "memory");
}

// ---------------------------------------------------------------------------
// GEMM: out[M,128] = act(A[M,128] @ W[128,128] + b [+ resid])
// W fully in SMEM (64KB). 256 thr/block, warp owns 4 rows.
// Inner product via packed fma.rn.f32x2 (2x fp32 FMA throughput).
// MODE 0: ReLU epilogue.   MODE 1: + residual epilogue.
// ---------------------------------------------------------------------------
template <int MODE>
__global__ void __launch_bounds__(256, 3)
gemm_kernel(const float* __restrict__ A, const float* __restrict__ W,
            const float* __restrict__ bias, const float* __restrict__ resid,
            float* __restrict__ out) {
    extern __shared__ float smem[];        // [128*128] W + [128] bias
    float* Ws = smem;
    float* bs = smem + D_DIM * D_DIM;

    int tid = threadIdx.x;
    {
        const float4* W4 = (const float4*)W;
        float4* Ws4 = (float4*)Ws;
        #pragma unroll
        for (int i = 0; i < 16; i++) Ws4[tid + i * 256] = W4[tid + i * 256];
        if (tid < 32) ((float4*)bs)[tid] = ((const float4*)bias)[tid];
    }
    __syncthreads();

    int warp = tid >> 5;
    int lane = tid & 31;
    int row0 = blockIdx.x * 32 + warp * 4;

    float4 x[4];
    #pragma unroll
    for (int r = 0; r < 4; r++) {
        int row = row0 + r;
        x[r] = (row < N_NODES)
                 ? ((const float4*)(A + (size_t)row * D_DIM))[lane]
                 : make_float4(0.f, 0.f, 0.f, 0.f);
    }

    unsigned long long acc[4][2];
    #pragma unroll
    for (int r = 0; r < 4; r++) { acc[r][0] = 0ull; acc[r][1] = 0ull; }

    const ulonglong2* Wp = (const ulonglong2*)Ws;

    #pragma unroll 4
    for (int kk = 0; kk < 32; kk++) {              // kk = owner lane of x_k
        float4 xb[4];
        #pragma unroll
        for (int r = 0; r < 4; r++) {
            xb[r].x = __shfl_sync(0xffffffffu, x[r].x, kk);
            xb[r].y = __shfl_sync(0xffffffffu, x[r].y, kk);
            xb[r].z = __shfl_sync(0xffffffffu, x[r].z, kk);
            xb[r].w = __shfl_sync(0xffffffffu, x[r].w, kk);
        }
        #pragma unroll
        for (int c = 0; c < 4; c++) {
            int k = kk * 4 + c;
            ulonglong2 w2 = Wp[k * 32 + lane];     // W[k][4*lane .. 4*lane+3]
            #pragma unroll
            for (int r = 0; r < 4; r++) {
                float xv = (c == 0) ? xb[r].x : (c == 1) ? xb[r].y
                         : (c == 2) ? xb[r].z : xb[r].w;
                unsigned long long xx = pack2(xv, xv);
                acc[r][0] = fma2(xx, w2.x, acc[r][0]);
                acc[r][1] = fma2(xx, w2.y, acc[r][1]);
            }
        }
    }

    int col = lane * 4;
    float4 bb = *(const float4*)(bs + col);
    #pragma unroll
    for (int r = 0; r < 4; r++) {
        int row = row0 + r;
        if (row >= N_NODES) continue;
        float2 lo = unpack2(acc[r][0]);
        float2 hi = unpack2(acc[r][1]);
        float4 o;
        o.x = lo.x + bb.x; o.y = lo.y + bb.y;
        o.z = hi.x + bb.z; o.w = hi.y + bb.w;
        if (MODE == 0) {
            o.x = fmaxf(o.x, 0.f); o.y = fmaxf(o.y, 0.f);
            o.z = fmaxf(o.z, 0.f); o.w = fmaxf(o.w, 0.f);
        } else {
            float4 r4 = ((const float4*)(resid + (size_t)row * D_DIM))[lane];
            o.x += r4.x; o.y += r4.y; o.z += r4.z; o.w += r4.w;
        }
        ((float4*)(out + (size_t)row * D_DIM))[lane] = o;
    }
}

// ---------------------------------------------------------------------------
extern "C" void kernel_launch(void* const* d_in, const int* in_sizes, int n_in,
                              void* d_out, int out_size) {
    const float* X   = (const float*)d_in[0];
    const void*  ei  = d_in[1];               // int32 or int64, probed on-device
    const float* eps = (const float*)d_in[2];
    const float* W1  = (const float*)d_in[3];
    const float* b1  = (const float*)d_in[4];
    const float* W2  = (const float*)d_in[5];
    const float* b2  = (const float*)d_in[6];
    float* out = (float*)d_out;

    float *zbuf, *hbuf, *xbuf;
    cudaGetSymbolAddress((void**)&zbuf, g_Z);
    cudaGetSymbolAddress((void**)&hbuf, g_H);
    cudaGetSymbolAddress((void**)&xbuf, g_X);

    const int SMEM = (D_DIM * D_DIM + D_DIM) * sizeof(float);  // 66048 B
    cudaFuncSetAttribute((const void*)gemm_kernel<0>,
                         cudaFuncAttributeMaxDynamicSharedMemorySize, SMEM);
    cudaFuncSetAttribute((const void*)gemm_kernel<1>,
                         cudaFuncAttributeMaxDynamicSharedMemorySize, SMEM);

    const int initBlocks    = (N_NODES * D_DIM / 4 + 255) / 256;   // 6250
    const int scatterBlocks = (E_EDGES * 32 + 255) / 256;          // 100000
    const int gemmBlocks    = (N_NODES + 31) / 32;                 // 1563

    detect_dtype_kernel<<<1, 256>>>(ei);

    for (int layer = 0; layer < L_LAYERS; layer++) {
        const float* Xcur = (layer == 0) ? X : xbuf;
        float* Xnext = (layer == L_LAYERS - 1) ? out : xbuf;

        init_z_kernel<<<initBlocks, 256>>>(Xcur, eps, layer);
        scatter_kernel<<<scatterBlocks, 256>>>(Xcur, ei);
        gemm_kernel<0><<<gemmBlocks, 256, SMEM>>>(
            zbuf, W1 + (size_t)layer * D_DIM * D_DIM, b1 + layer * D_DIM,
            nullptr, hbuf);
        gemm_kernel<1><<<gemmBlocks, 256, SMEM>>>(
            hbuf, W2 + (size_t)layer * D_DIM * D_DIM, b2 + layer * D_DIM,
            Xcur, Xnext);  // in-place safe: each thread reads its own resid row before writing
    }
}

// round 12
// speedup vs baseline: 1.0931x; 1.0931x over previous
#include <cuda_runtime.h>
#include <cstdint>

#define N_NODES 50000
#define E_EDGES 800000
#define D_DIM   128
#define L_LAYERS 3

// Scratch (static __device__ arrays: allocation-free per harness rules).
__device__ __align__(16) float g_Z[N_NODES * D_DIM];  // Z = (1+eps)*X + S
__device__ __align__(16) float g_H[N_NODES * D_DIM];  // hidden after ReLU
__device__ __align__(16) float g_X[N_NODES * D_DIM];  // ping buffer between layers
__device__ int g_is_i64;                              // edge_index dtype flag

// ---------------------------------------------------------------------------
// packed f32x2 helpers (Blackwell sm_103a)
// ---------------------------------------------------------------------------
__device__ __forceinline__ unsigned long long pack2(float a, float b) {
    unsigned long long r;
    asm("mov.b64 %0, {%1, %2};" : "=l"(r) : "f"(a), "f"(b));
    return r;
}
__device__ __forceinline__ unsigned long long fma2(unsigned long long a,
                                                   unsigned long long b,
                                                   unsigned long long c) {
    unsigned long long r;
    asm("fma.rn.f32x2 %0, %1, %2, %3;" : "=l"(r) : "l"(a), "l"(b), "l"(c));
    return r;
}
__device__ __forceinline__ float2 unpack2(unsigned long long v) {
    float2 r;
    asm("mov.b64 {%0, %1}, %2;" : "=f"(r.x), "=f"(r.y) : "l"(v));
    return r;
}

// ---------------------------------------------------------------------------
// Dtype probe (kept from R6: makes the kernel correct under int32 OR int64
// edge_index; misdetection probability ~1e-93).
// ---------------------------------------------------------------------------
__global__ void detect_dtype_kernel(const void* ei) {
    const long long* e64 = (const long long*)ei;
    int bad = 0;
    for (int i = threadIdx.x; i < 2048; i += 256) {
        long long v = e64[i];
        if (v < 0 || v >= N_NODES) bad = 1;
    }
    bad = __syncthreads_or(bad);
    if (threadIdx.x == 0) g_is_i64 = bad ? 0 : 1;
}

// ---------------------------------------------------------------------------
// Z = (1 + eps[layer]) * X   (needed only for layer 0; later layers get Z
// written by the previous MODE-1 GEMM epilogue)
// ---------------------------------------------------------------------------
__global__ void init_z_kernel(const float* __restrict__ X,
                              const float* __restrict__ eps, int layer) {
    int i = blockIdx.x * blockDim.x + threadIdx.x;
    const int total = N_NODES * D_DIM / 4;
    if (i >= total) return;
    float s = 1.0f + __ldg(eps + layer);
    float4 v = ((const float4*)X)[i];
    v.x *= s; v.y *= s; v.z *= s; v.w *= s;
    ((float4*)g_Z)[i] = v;
}

// ---------------------------------------------------------------------------
// Scatter-add: one warp per edge. Lane l handles columns [4l, 4l+4).
// Coalesced 512B gather of X[src]; 16B vector red to Z[dst].
// ---------------------------------------------------------------------------
__global__ void scatter_kernel(const float* __restrict__ X,
                               const void* __restrict__ ei) {
    unsigned e = (blockIdx.x * blockDim.x + threadIdx.x) >> 5;
    unsigned lane = threadIdx.x & 31u;
    if (e >= E_EDGES) return;
    int s, d;
    if (g_is_i64) {
        const long long* e64 = (const long long*)ei;
        s = (int)e64[e];
        d = (int)e64[E_EDGES + e];
    } else {
        const int* e32 = (const int*)ei;
        s = e32[e];
        d = e32[E_EDGES + e];
    }
    float4 v = ((const float4*)(X + (size_t)s * D_DIM))[lane];
    float* p = g_Z + (size_t)d * D_DIM + lane * 4;
    asm volatile("red.global.add.v4.f32 [%0], {%1, %2, %3, %4};"
                 :: "l"(p), "f"(v.x), "f"(v.y), "f"(v.z), "f"(v.w)
                 : "memory");
}

// ---------------------------------------------------------------------------
// GEMM: out[M,128] = act(A[M,128] @ W[128,128] + b [+ resid])
// R7 profile showed MIO-bound (L1=84%): W smem reads + SHFL dominate.
// Fix: 8 rows per warp (W crossbar traffic per row halved). occ 2, 128 regs.
// MODE 0: ReLU epilogue -> out.
// MODE 1: +resid epilogue -> out; if WZ also writes g_Z = (1+eps[next])*out
//         (replaces the next layer's init_z kernel).
// ---------------------------------------------------------------------------
template <int MODE, bool WZ>
__global__ void __launch_bounds__(256, 2)
gemm_kernel(const float* __restrict__ A, const float* __restrict__ W,
            const float* __restrict__ bias, const float* __restrict__ resid,
            float* __restrict__ out, const float* __restrict__ eps_next) {
    extern __shared__ float smem[];        // [128*128] W + [128] bias
    float* Ws = smem;
    float* bs = smem + D_DIM * D_DIM;

    int tid = threadIdx.x;
    {
        const float4* W4 = (const float4*)W;
        float4* Ws4 = (float4*)Ws;
        #pragma unroll
        for (int i = 0; i < 16; i++) Ws4[tid + i * 256] = W4[tid + i * 256];
        if (tid < 32) ((float4*)bs)[tid] = ((const float4*)bias)[tid];
    }
    __syncthreads();

    int warp = tid >> 5;
    int lane = tid & 31;
    int row0 = blockIdx.x * 64 + warp * 8;   // 8 rows per warp

    float4 x[8];
    #pragma unroll
    for (int r = 0; r < 8; r++) {
        int row = row0 + r;
        x[r] = (row < N_NODES)
                 ? ((const float4*)(A + (size_t)row * D_DIM))[lane]
                 : make_float4(0.f, 0.f, 0.f, 0.f);
    }

    unsigned long long acc[8][2];
    #pragma unroll
    for (int r = 0; r < 8; r++) { acc[r][0] = 0ull; acc[r][1] = 0ull; }

    const ulonglong2* Wp = (const ulonglong2*)Ws;

    #pragma unroll 4
    for (int kk = 0; kk < 32; kk++) {              // kk = owner lane of x_k
        float4 xb[8];
        #pragma unroll
        for (int r = 0; r < 8; r++) {
            xb[r].x = __shfl_sync(0xffffffffu, x[r].x, kk);
            xb[r].y = __shfl_sync(0xffffffffu, x[r].y, kk);
            xb[r].z = __shfl_sync(0xffffffffu, x[r].z, kk);
            xb[r].w = __shfl_sync(0xffffffffu, x[r].w, kk);
        }
        #pragma unroll
        for (int c = 0; c < 4; c++) {
            int k = kk * 4 + c;
            ulonglong2 w2 = Wp[k * 32 + lane];     // W[k][4*lane .. 4*lane+3]
            #pragma unroll
            for (int r = 0; r < 8; r++) {
                float xv = (c == 0) ? xb[r].x : (c == 1) ? xb[r].y
                         : (c == 2) ? xb[r].z : xb[r].w;
                unsigned long long xx = pack2(xv, xv);
                acc[r][0] = fma2(xx, w2.x, acc[r][0]);
                acc[r][1] = fma2(xx, w2.y, acc[r][1]);
            }
        }
    }

    int col = lane * 4;
    float4 bb = *(const float4*)(bs + col);
    float znext = WZ ? (1.0f + __ldg(eps_next)) : 0.0f;
    #pragma unroll
    for (int r = 0; r < 8; r++) {
        int row = row0 + r;
        if (row >= N_NODES) continue;
        float2 lo = unpack2(acc[r][0]);
        float2 hi = unpack2(acc[r][1]);
        float4 o;
        o.x = lo.x + bb.x; o.y = lo.y + bb.y;
        o.z = hi.x + bb.z; o.w = hi.y + bb.w;
        if (MODE == 0) {
            o.x = fmaxf(o.x, 0.f); o.y = fmaxf(o.y, 0.f);
            o.z = fmaxf(o.z, 0.f); o.w = fmaxf(o.w, 0.f);
        } else {
            float4 r4 = ((const float4*)(resid + (size_t)row * D_DIM))[lane];
            o.x += r4.x; o.y += r4.y; o.z += r4.z; o.w += r4.w;
        }
        ((float4*)(out + (size_t)row * D_DIM))[lane] = o;
        if (WZ) {
            float4 z;
            z.x = o.x * znext; z.y = o.y * znext;
            z.z = o.z * znext; z.w = o.w * znext;
            ((float4*)(g_Z + (size_t)row * D_DIM))[lane] = z;
        }
    }
}

// ---------------------------------------------------------------------------
extern "C" void kernel_launch(void* const* d_in, const int* in_sizes, int n_in,
                              void* d_out, int out_size) {
    const float* X   = (const float*)d_in[0];
    const void*  ei  = d_in[1];               // int32 or int64, probed on-device
    const float* eps = (const float*)d_in[2];
    const float* W1  = (const float*)d_in[3];
    const float* b1  = (const float*)d_in[4];
    const float* W2  = (const float*)d_in[5];
    const float* b2  = (const float*)d_in[6];
    float* out = (float*)d_out;

    float *zbuf, *hbuf, *xbuf;
    cudaGetSymbolAddress((void**)&zbuf, g_Z);
    cudaGetSymbolAddress((void**)&hbuf, g_H);
    cudaGetSymbolAddress((void**)&xbuf, g_X);

    const int SMEM = (D_DIM * D_DIM + D_DIM) * sizeof(float);  // 66048 B
    cudaFuncSetAttribute((const void*)gemm_kernel<0, false>,
                         cudaFuncAttributeMaxDynamicSharedMemorySize, SMEM);
    cudaFuncSetAttribute((const void*)gemm_kernel<1, false>,
                         cudaFuncAttributeMaxDynamicSharedMemorySize, SMEM);
    cudaFuncSetAttribute((const void*)gemm_kernel<1, true>,
                         cudaFuncAttributeMaxDynamicSharedMemorySize, SMEM);

    const int initBlocks    = (N_NODES * D_DIM / 4 + 255) / 256;   // 6250
    const int scatterBlocks = (E_EDGES * 32 + 255) / 256;          // 100000
    const int gemmBlocks    = (N_NODES + 63) / 64;                 // 782

    detect_dtype_kernel<<<1, 256>>>(ei);

    for (int layer = 0; layer < L_LAYERS; layer++) {
        const float* Xcur = (layer == 0) ? X : xbuf;
        float* Xnext = (layer == L_LAYERS - 1) ? out : xbuf;

        if (layer == 0)
            init_z_kernel<<<initBlocks, 256>>>(Xcur, eps, 0);
        // layers 1,2: g_Z pre-written by previous gemm<1,true> epilogue

        scatter_kernel<<<scatterBlocks, 256>>>(Xcur, ei);
        gemm_kernel<0, false><<<gemmBlocks, 256, SMEM>>>(
            zbuf, W1 + (size_t)layer * D_DIM * D_DIM, b1 + layer * D_DIM,
            nullptr, hbuf, nullptr);
        if (layer < L_LAYERS - 1)
            gemm_kernel<1, true><<<gemmBlocks, 256, SMEM>>>(
                hbuf, W2 + (size_t)layer * D_DIM * D_DIM, b2 + layer * D_DIM,
                Xcur, Xnext, eps + layer + 1);
        else
            gemm_kernel<1, false><<<gemmBlocks, 256, SMEM>>>(
                hbuf, W2 + (size_t)layer * D_DIM * D_DIM, b2 + layer * D_DIM,
                Xcur, Xnext, nullptr);
    }
}